// round 8
// baseline (speedup 1.0000x reference)
#include <cuda_runtime.h>

// ---------------------------------------------------------------------------
// ComputeAlignmentError on GB300 (sm_103a).
// err[b,i,j] = || Ep_j(cp_i - op_j) - Et_j(ct_i - ot_j) + eps ||_2 * m_i * m_j
// R8 reformulation: Ep_j is orthonormal (e1 perp e2, e3 = e1 x e2), so rotate
// by Ep^T (norm-preserving):
//   err = || cp_i - M_j ct_i + w_j ||,  M_j = Ep^T Et,
//   w_j = -op_j + M_j ot_j + eps * rowsum(Ep_j)
// Per-j consts 22 -> 13 floats, math 24 -> 16 packed f32x2 ops / 2 outputs.
// i-data pre-paired in gmem -> 4x LDS.128 broadcast per iteration.
// mask arrives as int32 (bool promoted by harness).
// ---------------------------------------------------------------------------

#define MAX_BN 8192
__device__ float4 g_jc2[MAX_BN * 4];        // per-j: -M(9), w(3), mask (16 floats)
__device__ float4 g_ic2[(MAX_BN / 2) * 4];  // per-i-PAIR: cpx2,cpy2,cpz2,mi2,ctx2,cty2,ctz2,pad2

struct V3 { float x, y, z; };
__device__ __forceinline__ V3 v3(float x, float y, float z) { V3 v; v.x = x; v.y = y; v.z = z; return v; }
__device__ __forceinline__ V3 vsub(V3 a, V3 b) { return v3(a.x - b.x, a.y - b.y, a.z - b.z); }
__device__ __forceinline__ V3 vadd(V3 a, V3 b) { return v3(a.x + b.x, a.y + b.y, a.z + b.z); }
__device__ __forceinline__ float dot3(V3 a, V3 b) { return a.x * b.x + a.y * b.y + a.z * b.z; }
__device__ __forceinline__ V3 vnrm(V3 a) {
    float nn = sqrtf(dot3(a, a));
    float inv = 1.0f / fmaxf(nn, 1e-8f);
    return v3(a.x * inv, a.y * inv, a.z * inv);
}
__device__ __forceinline__ V3 vcross(V3 a, V3 b) {
    return v3(a.y * b.z - a.z * b.y,
              a.z * b.x - a.x * b.z,
              a.x * b.y - a.y * b.x);
}

__device__ __forceinline__ void frame_basis(const float* __restrict__ F,
                                            V3& o, V3& e1, V3& e2, V3& e3) {
    V3 a = v3(F[0], F[3], F[6]);
    V3 b = v3(F[1], F[4], F[7]);
    V3 c = v3(F[2], F[5], F[8]);
    V3 w1 = vnrm(vsub(a, b));
    V3 w2 = vnrm(vsub(c, b));
    e1 = vnrm(vadd(w1, w2));
    e2 = vnrm(vsub(w2, w1));
    e3 = vcross(e1, e2);
    o = b;
}

__global__ void precompute_kernel(const float* __restrict__ pc, const float* __restrict__ tc,
                                  const float* __restrict__ pf, const float* __restrict__ tf,
                                  const int* __restrict__ mask, int bn) {
    int t = blockIdx.x * blockDim.x + threadIdx.x;
    if (t >= bn) return;
    V3 op, p1, p2, p3, ot, t1, t2, t3;
    frame_basis(pf + (size_t)t * 9, op, p1, p2, p3);
    frame_basis(tf + (size_t)t * 9, ot, t1, t2, t3);
    float mf = (mask[t] != 0) ? 1.0f : 0.0f;
    const float eps = 1e-8f;

    // M = Ep^T Et  (M[a][b] = sum_k Ep_k[a] * Et_k[b])
    float M[3][3];
    float P[3][3] = {{p1.x, p1.y, p1.z}, {p2.x, p2.y, p2.z}, {p3.x, p3.y, p3.z}};
    float T[3][3] = {{t1.x, t1.y, t1.z}, {t2.x, t2.y, t2.z}, {t3.x, t3.y, t3.z}};
    #pragma unroll
    for (int a = 0; a < 3; ++a)
        #pragma unroll
        for (int bcol = 0; bcol < 3; ++bcol)
            M[a][bcol] = P[0][a] * T[0][bcol] + P[1][a] * T[1][bcol] + P[2][a] * T[2][bcol];

    // w = -op + M*ot + eps * rowsum(Ep)  (rowsum = Ep^T * ones)
    float otv[3] = {ot.x, ot.y, ot.z};
    float opv[3] = {op.x, op.y, op.z};
    float w[3];
    #pragma unroll
    for (int a = 0; a < 3; ++a) {
        float s = P[0][a] + P[1][a] + P[2][a];
        w[a] = -opv[a] + M[a][0] * otv[0] + M[a][1] * otv[1] + M[a][2] * otv[2] + eps * s;
    }

    float4* jp = g_jc2 + (size_t)t * 4;
    jp[0] = make_float4(-M[0][0], -M[0][1], -M[0][2], w[0]);
    jp[1] = make_float4(-M[1][0], -M[1][1], -M[1][2], w[1]);
    jp[2] = make_float4(-M[2][0], -M[2][1], -M[2][2], w[2]);
    jp[3] = make_float4(mf, 0.0f, 0.0f, 0.0f);

    // paired i-layout: pair p holds i=2p (h=0) and i=2p+1 (h=1)
    const float* cpp = pc + (size_t)t * 3;
    const float* ctp = tc + (size_t)t * 3;
    float* ib = (float*)(g_ic2 + (size_t)(t >> 1) * 4);
    int h = t & 1;
    ib[0 + h]  = cpp[0];
    ib[2 + h]  = cpp[1];
    ib[4 + h]  = cpp[2];
    ib[6 + h]  = mf;
    ib[8 + h]  = ctp[0];
    ib[10 + h] = ctp[1];
    ib[12 + h] = ctp[2];
    ib[14 + h] = 0.0f;
}

// ---- packed f32x2 helpers (Blackwell) ----
typedef unsigned long long ull;
__device__ __forceinline__ ull pk2(float lo, float hi) {
    ull r; asm("mov.b64 %0, {%1, %2};" : "=l"(r) : "f"(lo), "f"(hi)); return r;
}
__device__ __forceinline__ void unpk2(ull v, float& lo, float& hi) {
    asm("mov.b64 {%0, %1}, %2;" : "=f"(lo), "=f"(hi) : "l"(v));
}
__device__ __forceinline__ ull fma2(ull a, ull b, ull c) {
    ull d; asm("fma.rn.f32x2 %0, %1, %2, %3;" : "=l"(d) : "l"(a), "l"(b), "l"(c)); return d;
}
__device__ __forceinline__ ull add2(ull a, ull b) {
    ull d; asm("add.rn.f32x2 %0, %1, %2;" : "=l"(d) : "l"(a), "l"(b)); return d;
}
__device__ __forceinline__ ull mul2(ull a, ull b) {
    ull d; asm("mul.rn.f32x2 %0, %1, %2;" : "=l"(d) : "l"(a), "l"(b)); return d;
}
__device__ __forceinline__ float sqrt_approx(float s) {
    float r; asm("sqrt.approx.f32 %0, %1;" : "=f"(r) : "f"(s)); return r;
}

#define JT 128   // j-tile = blockDim.x (lane-major -> coalesced stores)
#define IT 32    // i-tile; 2048 blocks at n=2048

__global__ void __launch_bounds__(JT, 9) pair_kernel(float* __restrict__ out, int n) {
    __shared__ __align__(16) float4 sI[(IT / 2) * 4];  // packed i-pairs

    int bb    = blockIdx.z;
    int j     = blockIdx.x * JT + threadIdx.x;
    int ibase = blockIdx.y * IT;
    int base  = bb * n;
    int iend  = min(IT, n - ibase);
    int npair = iend >> 1;

    // stage i-pairs (ibase and base*n both even by construction; n assumed even)
    int nload = ((iend + 1) >> 1) * 4;
    if (threadIdx.x < nload) {
        size_t pb = (size_t)(base + ibase) >> 1;
        sI[threadIdx.x] = g_ic2[pb * 4 + threadIdx.x];
    }

    bool jok = j < n;
    const float4* jp = g_jc2 + (size_t)(base + (jok ? j : 0)) * 4;
    float4 f0 = jp[0], f1 = jp[1], f2 = jp[2], f3 = jp[3];
    ull G00 = pk2(f0.x, f0.x), G01 = pk2(f0.y, f0.y), G02 = pk2(f0.z, f0.z), W0 = pk2(f0.w, f0.w);
    ull G10 = pk2(f1.x, f1.x), G11 = pk2(f1.y, f1.y), G12 = pk2(f1.z, f1.z), W1 = pk2(f1.w, f1.w);
    ull G20 = pk2(f2.x, f2.x), G21 = pk2(f2.y, f2.y), G22 = pk2(f2.z, f2.z), W2 = pk2(f2.w, f2.w);
    ull MJ2 = pk2(f3.x, f3.x);
    __syncthreads();

    const ull* S = (const ull*)sI;   // 8 ulls per pair
    float* orow = out + (size_t)(base + ibase) * n + j;
    long long nn = n;

    #pragma unroll 2
    for (int p = 0; p < npair; ++p) {
        ull CPX = S[p * 8 + 0], CPY = S[p * 8 + 1];
        ull CPZ = S[p * 8 + 2], MI  = S[p * 8 + 3];
        ull CTX = S[p * 8 + 4], CTY = S[p * 8 + 5];
        ull CTZ = S[p * 8 + 6];
        ull x0 = fma2(G00, CTX, fma2(G01, CTY, fma2(G02, CTZ, add2(CPX, W0))));
        ull x1 = fma2(G10, CTX, fma2(G11, CTY, fma2(G12, CTZ, add2(CPY, W1))));
        ull x2 = fma2(G20, CTX, fma2(G21, CTY, fma2(G22, CTZ, add2(CPZ, W2))));
        ull s2 = fma2(x0, x0, fma2(x1, x1, mul2(x2, x2)));
        ull m2 = mul2(MI, MJ2);
        float slo, shi, mlo, mhi;
        unpk2(s2, slo, shi);
        unpk2(m2, mlo, mhi);
        float rlo = sqrt_approx(slo) * mlo;
        float rhi = sqrt_approx(shi) * mhi;
        if (jok) { orow[0] = rlo; orow[nn] = rhi; }
        orow += 2 * nn;
    }
    // odd tail (n odd or partial tile)
    if (iend & 1) {
        const float* sf = (const float*)sI;
        int p = iend >> 1;              // last element is i=2p (h=0)
        float Ax = sf[p * 16 + 0],  Ay = sf[p * 16 + 2],  Az = sf[p * 16 + 4];
        float mi = sf[p * 16 + 6];
        float Bx = sf[p * 16 + 8],  By = sf[p * 16 + 10], Bz = sf[p * 16 + 12];
        float x0 = fmaf(f0.x, Bx, fmaf(f0.y, By, fmaf(f0.z, Bz, Ax + f0.w)));
        float x1 = fmaf(f1.x, Bx, fmaf(f1.y, By, fmaf(f1.z, Bz, Ay + f1.w)));
        float x2 = fmaf(f2.x, Bx, fmaf(f2.y, By, fmaf(f2.z, Bz, Az + f2.w)));
        float s = fmaf(x0, x0, fmaf(x1, x1, x2 * x2));
        float r = sqrt_approx(s) * mi * f3.x;
        if (jok) orow[0] = r;
    }
}

extern "C" void kernel_launch(void* const* d_in, const int* in_sizes, int n_in,
                              void* d_out, int out_size) {
    const float* pc = (const float*)d_in[0];
    const float* tc = (const float*)d_in[1];
    const float* pf = (const float*)d_in[2];
    const float* tf = (const float*)d_in[3];
    const int*   mask = (const int*)d_in[4];
    int bn = in_sizes[4];
    int n  = (int)((long long)out_size / (long long)bn);
    int b  = bn / n;

    precompute_kernel<<<(bn + 127) / 128, 128>>>(pc, tc, pf, tf, mask, bn);
    dim3 grid((n + JT - 1) / JT, (n + IT - 1) / IT, b);
    pair_kernel<<<grid, JT>>>((float*)d_out, n);
}

// round 9
// speedup vs baseline: 1.1530x; 1.1530x over previous
#include <cuda_runtime.h>

// ---------------------------------------------------------------------------
// ComputeAlignmentError on GB300 (sm_103a) - R9: single fused kernel.
// err[b,i,j] = || cp_i - M_j ct_i + w_j || * m_i * m_j   (rotated form,
//   M_j = Ep^T Et orthonormal-rotation trick, w = -op + M ot + eps*rowsum(Ep))
// Block = 32 j x 256 i. Warp0 computes the block's 32 j-constant sets (13
// floats each) while warps 1-3 stage the i-tile into SoA smem; then all 4
// warps run the packed f32x2 pair loop warp-strided over i-pairs.
// One launch total (R8 had 4.6us of precompute+launch overhead).
// mask arrives as int32 (bool promoted by harness).
// ---------------------------------------------------------------------------

typedef unsigned long long ull;
__device__ __forceinline__ ull pk2(float lo, float hi) {
    ull r; asm("mov.b64 %0, {%1, %2};" : "=l"(r) : "f"(lo), "f"(hi)); return r;
}
__device__ __forceinline__ void unpk2(ull v, float& lo, float& hi) {
    asm("mov.b64 {%0, %1}, %2;" : "=f"(lo), "=f"(hi) : "l"(v));
}
__device__ __forceinline__ ull fma2(ull a, ull b, ull c) {
    ull d; asm("fma.rn.f32x2 %0, %1, %2, %3;" : "=l"(d) : "l"(a), "l"(b), "l"(c)); return d;
}
__device__ __forceinline__ ull add2(ull a, ull b) {
    ull d; asm("add.rn.f32x2 %0, %1, %2;" : "=l"(d) : "l"(a), "l"(b)); return d;
}
__device__ __forceinline__ ull mul2(ull a, ull b) {
    ull d; asm("mul.rn.f32x2 %0, %1, %2;" : "=l"(d) : "l"(a), "l"(b)); return d;
}
__device__ __forceinline__ float sqrt_approx(float s) {
    float r; asm("sqrt.approx.f32 %0, %1;" : "=f"(r) : "f"(s)); return r;
}

struct V3 { float x, y, z; };
__device__ __forceinline__ V3 v3(float x, float y, float z) { V3 v; v.x = x; v.y = y; v.z = z; return v; }
__device__ __forceinline__ V3 vsub(V3 a, V3 b) { return v3(a.x - b.x, a.y - b.y, a.z - b.z); }
__device__ __forceinline__ V3 vadd(V3 a, V3 b) { return v3(a.x + b.x, a.y + b.y, a.z + b.z); }
__device__ __forceinline__ float dot3(V3 a, V3 b) { return a.x * b.x + a.y * b.y + a.z * b.z; }
__device__ __forceinline__ V3 vnrm(V3 a) {
    float nn = sqrtf(dot3(a, a));
    float inv = 1.0f / fmaxf(nn, 1e-8f);
    return v3(a.x * inv, a.y * inv, a.z * inv);
}
__device__ __forceinline__ V3 vcross(V3 a, V3 b) {
    return v3(a.y * b.z - a.z * b.y,
              a.z * b.x - a.x * b.z,
              a.x * b.y - a.y * b.x);
}
__device__ __forceinline__ void frame_basis(const float* __restrict__ F,
                                            V3& o, V3& e1, V3& e2, V3& e3) {
    V3 a = v3(F[0], F[3], F[6]);
    V3 b = v3(F[1], F[4], F[7]);
    V3 c = v3(F[2], F[5], F[8]);
    V3 w1 = vnrm(vsub(a, b));
    V3 w2 = vnrm(vsub(c, b));
    e1 = vnrm(vadd(w1, w2));
    e2 = vnrm(vsub(w2, w1));
    e3 = vcross(e1, e2);
    o = b;
}

#define JB 32    // j per block (= warp width -> coalesced 128B stores)
#define IT 256   // i per block
#define NT 128   // threads per block (4 warps; warps split the i-pairs)

__global__ void __launch_bounds__(NT, 8) fused_kernel(
    float* __restrict__ out,
    const float* __restrict__ pc, const float* __restrict__ tc,
    const float* __restrict__ pf, const float* __restrict__ tf,
    const int* __restrict__ mask, int n)
{
    __shared__ __align__(16) float s_jc[13 * JB];                 // SoA j-consts
    __shared__ __align__(16) float s_px[IT], s_py[IT], s_pz[IT], s_mi[IT];
    __shared__ __align__(16) float s_tx[IT], s_ty[IT], s_tz[IT];

    int tid   = threadIdx.x;
    int lane  = tid & 31;
    int wid   = tid >> 5;
    int bb    = blockIdx.z;
    int jbase = blockIdx.x * JB;
    int ibase = blockIdx.y * IT;
    int base  = bb * n;
    int iend  = min(IT, n - ibase);

    if (wid == 0) {
        // ---- per-j constants for this block's 32 j's (one lane = one j) ----
        int j = jbase + lane;
        float C[13];
        if (j < n) {
            int g = base + j;
            V3 op, p1, p2, p3, ot, t1, t2, t3;
            frame_basis(pf + (size_t)g * 9, op, p1, p2, p3);
            frame_basis(tf + (size_t)g * 9, ot, t1, t2, t3);
            float mf = (mask[g] != 0) ? 1.0f : 0.0f;
            const float eps = 1e-8f;
            float P[3][3] = {{p1.x, p1.y, p1.z}, {p2.x, p2.y, p2.z}, {p3.x, p3.y, p3.z}};
            float T[3][3] = {{t1.x, t1.y, t1.z}, {t2.x, t2.y, t2.z}, {t3.x, t3.y, t3.z}};
            float M[3][3];
            #pragma unroll
            for (int a = 0; a < 3; ++a)
                #pragma unroll
                for (int c = 0; c < 3; ++c)
                    M[a][c] = P[0][a] * T[0][c] + P[1][a] * T[1][c] + P[2][a] * T[2][c];
            float otv[3] = {ot.x, ot.y, ot.z};
            float opv[3] = {op.x, op.y, op.z};
            #pragma unroll
            for (int a = 0; a < 3; ++a) {
                float rs = P[0][a] + P[1][a] + P[2][a];
                float w  = -opv[a] + M[a][0] * otv[0] + M[a][1] * otv[1]
                         + M[a][2] * otv[2] + eps * rs;
                C[a * 3 + 0] = -M[a][0];
                C[a * 3 + 1] = -M[a][1];
                C[a * 3 + 2] = -M[a][2];
                C[9 + a]     = w;
            }
            C[12] = mf;
        } else {
            #pragma unroll
            for (int c = 0; c < 13; ++c) C[c] = 0.0f;
        }
        #pragma unroll
        for (int c = 0; c < 13; ++c) s_jc[c * JB + lane] = C[c];
    } else {
        // ---- stage i-tile into SoA smem (96 threads) ----
        for (int k = tid - 32; k < iend; k += NT - 32) {
            int gi = base + ibase + k;
            const float* cp = pc + (size_t)gi * 3;
            const float* ct = tc + (size_t)gi * 3;
            s_px[k] = cp[0]; s_py[k] = cp[1]; s_pz[k] = cp[2];
            s_tx[k] = ct[0]; s_ty[k] = ct[1]; s_tz[k] = ct[2];
            s_mi[k] = (mask[gi] != 0) ? 1.0f : 0.0f;
        }
    }
    __syncthreads();

    int j    = jbase + lane;
    bool jok = j < n;
    float c00 = s_jc[0*JB+lane], c01 = s_jc[1*JB+lane], c02 = s_jc[2*JB+lane];
    float c10 = s_jc[3*JB+lane], c11 = s_jc[4*JB+lane], c12 = s_jc[5*JB+lane];
    float c20 = s_jc[6*JB+lane], c21 = s_jc[7*JB+lane], c22 = s_jc[8*JB+lane];
    float w0  = s_jc[9*JB+lane], w1  = s_jc[10*JB+lane], w2 = s_jc[11*JB+lane];
    float mjf = s_jc[12*JB+lane];

    ull G00 = pk2(c00, c00), G01 = pk2(c01, c01), G02 = pk2(c02, c02);
    ull G10 = pk2(c10, c10), G11 = pk2(c11, c11), G12 = pk2(c12, c12);
    ull G20 = pk2(c20, c20), G21 = pk2(c21, c21), G22 = pk2(c22, c22);
    ull W0  = pk2(w0, w0),   W1  = pk2(w1, w1),   W2  = pk2(w2, w2);
    ull MJ2 = pk2(mjf, mjf);

    const ull* Px = (const ull*)s_px; const ull* Py = (const ull*)s_py;
    const ull* Pz = (const ull*)s_pz; const ull* Tx = (const ull*)s_tx;
    const ull* Ty = (const ull*)s_ty; const ull* Tz = (const ull*)s_tz;
    const ull* Mi = (const ull*)s_mi;

    long long nn = n;
    int npair = iend >> 1;
    float* obase = out + (size_t)(base + ibase) * n + j;
    float* orow  = obase + (size_t)(2 * wid) * nn;

    // warps split pairs: warp w takes p = w, w+4, w+8, ...
    #pragma unroll 4
    for (int p = wid; p < npair; p += 4) {
        ull CPX = Px[p], CPY = Py[p], CPZ = Pz[p], MI = Mi[p];
        ull CTX = Tx[p], CTY = Ty[p], CTZ = Tz[p];
        ull x0 = fma2(G00, CTX, fma2(G01, CTY, fma2(G02, CTZ, add2(CPX, W0))));
        ull x1 = fma2(G10, CTX, fma2(G11, CTY, fma2(G12, CTZ, add2(CPY, W1))));
        ull x2 = fma2(G20, CTX, fma2(G21, CTY, fma2(G22, CTZ, add2(CPZ, W2))));
        ull s2 = fma2(x0, x0, fma2(x1, x1, mul2(x2, x2)));
        ull m2 = mul2(MI, MJ2);
        float slo, shi, mlo, mhi;
        unpk2(s2, slo, shi);
        unpk2(m2, mlo, mhi);
        float rlo = sqrt_approx(slo) * mlo;
        float rhi = sqrt_approx(shi) * mhi;
        if (jok) { orow[0] = rlo; orow[nn] = rhi; }
        orow += 8 * nn;   // 4 pairs = 8 rows per strided step
    }

    // odd tail (partial tile or odd n): last element i = iend-1
    if ((iend & 1) && wid == 0) {
        int it = iend - 1;
        float Ax = s_px[it], Ay = s_py[it], Az = s_pz[it], mi = s_mi[it];
        float Bx = s_tx[it], By = s_ty[it], Bz = s_tz[it];
        float x0 = fmaf(c00, Bx, fmaf(c01, By, fmaf(c02, Bz, Ax + w0)));
        float x1 = fmaf(c10, Bx, fmaf(c11, By, fmaf(c12, Bz, Ay + w1)));
        float x2 = fmaf(c20, Bx, fmaf(c21, By, fmaf(c22, Bz, Az + w2)));
        float s  = fmaf(x0, x0, fmaf(x1, x1, x2 * x2));
        float r  = sqrt_approx(s) * mi * mjf;
        if (jok) obase[(size_t)it * nn] = r;
    }
}

extern "C" void kernel_launch(void* const* d_in, const int* in_sizes, int n_in,
                              void* d_out, int out_size) {
    const float* pc = (const float*)d_in[0];
    const float* tc = (const float*)d_in[1];
    const float* pf = (const float*)d_in[2];
    const float* tf = (const float*)d_in[3];
    const int*   mask = (const int*)d_in[4];
    int bn = in_sizes[4];
    int n  = (int)((long long)out_size / (long long)bn);
    int b  = bn / n;

    dim3 grid((n + JB - 1) / JB, (n + IT - 1) / IT, b);
    fused_kernel<<<grid, NT>>>((float*)d_out, pc, tc, pf, tf, mask, n);
}